// round 2
// baseline (speedup 1.0000x reference)
#include <cuda_runtime.h>
#include <math.h>

#define B 256
#define S 512
#define IN 64
#define H 1024
#define KTOT (IN + H)   // 1088
#define HEAD 128
#define OUT 64

// ---------------- device scratch (static, no allocations) ----------------
__device__ float g_h[2][B * H];                  // ping-pong hidden state
__device__ float g_c[B * H];                     // cell state
__device__ float g_hall[(size_t)S * B * H];      // all hidden states: 512 MB
__device__ float g_P[(size_t)S * B * HEAD];      // relu(h @ Wd.T + bd): 64 MB

__device__ __forceinline__ float sigf(float x) { return 1.0f / (1.0f + expf(-x)); }

// ---------------- zero init (h0, c0) ----------------
__global__ void zero_kernel() {
    int i = blockIdx.x * blockDim.x + threadIdx.x;
    const int n = B * H;
    for (int idx = i; idx < n; idx += gridDim.x * blockDim.x) {
        g_h[0][idx] = 0.f;
        g_c[idx] = 0.f;
    }
}

// ---------------- per-step fused gate GEMM + LSTM update ----------------
// C[256,4096] = [x_t | h_prev] @ [W_ih | W_hh]^T + (b_ih + b_hh), then pointwise LSTM.
// Block tile: 64 batch rows x 16 hidden units (= 64 gate columns across the 4 gates).
// Grid: (B/64, H/16) = (4, 64) = 256 blocks. 256 threads; each thread: 4 batch rows x
// 1 hidden unit x 4 gates = 16 accumulators -> full LSTM update in the epilogue.
__global__ __launch_bounds__(256) void lstm_step(
    const float* __restrict__ x, const float* __restrict__ Wih,
    const float* __restrict__ bih, const float* __restrict__ Whh,
    const float* __restrict__ bhh, int t)
{
    __shared__ float As[16][68];   // [k][batch row]
    __shared__ float Bs[16][68];   // [k][gate-col r: gate = r/16, jl = r%16]

    const float* __restrict__ hprev = g_h[t & 1];
    float* __restrict__ hnext = g_h[(t & 1) ^ 1];

    const int tid = threadIdx.x;
    const int bm0 = blockIdx.x * 64;   // batch tile origin
    const int j0  = blockIdx.y * 16;   // hidden tile origin

    // loader mapping: each thread loads one float4 per tile (64 rows x 16 k)
    const int lm = tid >> 2;           // 0..63
    const int lk = (tid & 3) << 2;     // 0,4,8,12
    const int l_gate = lm >> 4;
    const int l_jl   = lm & 15;
    const int grow_l = l_gate * H + j0 + l_jl;   // W row for B-tile loads

    // compute mapping
    const int m0 = (tid >> 4) << 2;    // batch sub-row base: 0,4,...,60
    const int jl = tid & 15;           // hidden unit within tile

    float acc[4][4];                   // [batch sub-row][gate]
#pragma unroll
    for (int i = 0; i < 4; i++)
#pragma unroll
        for (int g = 0; g < 4; g++) acc[i][g] = 0.f;

    for (int kk = 0; kk < KTOT; kk += 16) {
        // stage global loads into registers (overlaps with previous compute)
        float4 av, bv;
        if (kk < IN) {
            av = *(const float4*)(x + ((size_t)(bm0 + lm) * S + t) * IN + kk + lk);
            bv = *(const float4*)(Wih + (size_t)grow_l * IN + kk + lk);
        } else {
            av = *(const float4*)(hprev + (size_t)(bm0 + lm) * H + (kk - IN) + lk);
            bv = *(const float4*)(Whh + (size_t)grow_l * H + (kk - IN) + lk);
        }
        __syncthreads();   // previous chunk's compute finished
        As[lk + 0][lm] = av.x; As[lk + 1][lm] = av.y;
        As[lk + 2][lm] = av.z; As[lk + 3][lm] = av.w;
        Bs[lk + 0][lm] = bv.x; Bs[lk + 1][lm] = bv.y;
        Bs[lk + 2][lm] = bv.z; Bs[lk + 3][lm] = bv.w;
        __syncthreads();

#pragma unroll
        for (int k = 0; k < 16; k++) {
            float4 a4 = *(const float4*)&As[k][m0];
#pragma unroll
            for (int g = 0; g < 4; g++) {
                float bvv = Bs[k][jl + (g << 4)];
                acc[0][g] += a4.x * bvv;
                acc[1][g] += a4.y * bvv;
                acc[2][g] += a4.z * bvv;
                acc[3][g] += a4.w * bvv;
            }
        }
    }

    // ---- epilogue: bias + LSTM pointwise ----
    const int jg = j0 + jl;
    float bias[4];
#pragma unroll
    for (int g = 0; g < 4; g++) {
        int grow = g * H + jg;
        bias[g] = bih[grow] + bhh[grow];
    }
#pragma unroll
    for (int i = 0; i < 4; i++) {
        int b = bm0 + m0 + i;
        float ig = acc[i][0] + bias[0];
        float fg = acc[i][1] + bias[1];
        float gg = acc[i][2] + bias[2];
        float og = acc[i][3] + bias[3];
        int idx = b * H + jg;
        float c_old = g_c[idx];
        float cn = sigf(fg) * c_old + sigf(ig) * tanhf(gg);
        float hn = sigf(og) * tanhf(cn);
        g_c[idx] = cn;
        hnext[idx] = hn;
        g_hall[(size_t)t * (B * H) + idx] = hn;
    }
}

// ---------------- dense1: P = relu(h_all @ Wd^T + bd), M=131072, N=128, K=1024 ----
// Tile 128x128, 256 threads, each 8x8. Grid 1024 blocks.
__global__ __launch_bounds__(256) void dense1(
    const float* __restrict__ Wd, const float* __restrict__ bd)
{
    __shared__ float As[8][132];
    __shared__ float Bs[8][132];
    const int tid = threadIdx.x;
    const int row0 = blockIdx.x * 128;
    const int lm = tid >> 1;           // 0..127
    const int lk = (tid & 1) << 2;     // 0,4
    const int m0 = (tid >> 4) << 3;
    const int n0 = (tid & 15) << 3;

    float acc[8][8];
#pragma unroll
    for (int i = 0; i < 8; i++)
#pragma unroll
        for (int j = 0; j < 8; j++) acc[i][j] = 0.f;

    for (int kk = 0; kk < H; kk += 8) {
        float4 av = *(const float4*)(g_hall + (size_t)(row0 + lm) * H + kk + lk);
        float4 bv = *(const float4*)(Wd + (size_t)lm * H + kk + lk);
        __syncthreads();
        As[lk + 0][lm] = av.x; As[lk + 1][lm] = av.y;
        As[lk + 2][lm] = av.z; As[lk + 3][lm] = av.w;
        Bs[lk + 0][lm] = bv.x; Bs[lk + 1][lm] = bv.y;
        Bs[lk + 2][lm] = bv.z; Bs[lk + 3][lm] = bv.w;
        __syncthreads();
#pragma unroll
        for (int k = 0; k < 8; k++) {
            float4 a0 = *(const float4*)&As[k][m0];
            float4 a1 = *(const float4*)&As[k][m0 + 4];
            float4 b0 = *(const float4*)&Bs[k][n0];
            float4 b1 = *(const float4*)&Bs[k][n0 + 4];
            float a[8] = {a0.x, a0.y, a0.z, a0.w, a1.x, a1.y, a1.z, a1.w};
            float bb[8] = {b0.x, b0.y, b0.z, b0.w, b1.x, b1.y, b1.z, b1.w};
#pragma unroll
            for (int mi = 0; mi < 8; mi++)
#pragma unroll
                for (int ni = 0; ni < 8; ni++) acc[mi][ni] += a[mi] * bb[ni];
        }
    }

#pragma unroll
    for (int mi = 0; mi < 8; mi++) {
        size_t r = (size_t)(row0 + m0 + mi);
#pragma unroll
        for (int ni = 0; ni < 8; ni++) {
            int n = n0 + ni;
            float v = acc[mi][ni] + bd[n];
            g_P[r * HEAD + n] = v > 0.f ? v : 0.f;
        }
    }
}

// ---------------- dense2: out = P @ W2^T + b2, M=131072, N=64, K=128 ----------------
// Tile 64x64, 256 threads, each 4x4. Grid 2048 blocks. Writes with [B,S,OUT] layout.
__global__ __launch_bounds__(256) void dense2(
    const float* __restrict__ W2, const float* __restrict__ b2,
    float* __restrict__ out)
{
    __shared__ float As[16][68];
    __shared__ float Bs[16][68];
    const int tid = threadIdx.x;
    const int row0 = blockIdx.x * 64;
    const int lm = tid >> 2;          // 0..63
    const int lk = (tid & 3) << 2;    // 0,4,8,12
    const int m0 = (tid >> 4) << 2;
    const int n0 = (tid & 15) << 2;

    float acc[4][4];
#pragma unroll
    for (int i = 0; i < 4; i++)
#pragma unroll
        for (int j = 0; j < 4; j++) acc[i][j] = 0.f;

    for (int kk = 0; kk < HEAD; kk += 16) {
        float4 av = *(const float4*)(g_P + (size_t)(row0 + lm) * HEAD + kk + lk);
        float4 bv = *(const float4*)(W2 + (size_t)lm * HEAD + kk + lk);
        __syncthreads();
        As[lk + 0][lm] = av.x; As[lk + 1][lm] = av.y;
        As[lk + 2][lm] = av.z; As[lk + 3][lm] = av.w;
        Bs[lk + 0][lm] = bv.x; Bs[lk + 1][lm] = bv.y;
        Bs[lk + 2][lm] = bv.z; Bs[lk + 3][lm] = bv.w;
        __syncthreads();
#pragma unroll
        for (int k = 0; k < 16; k++) {
            float4 a4 = *(const float4*)&As[k][m0];
            float4 b4 = *(const float4*)&Bs[k][n0];
            float a[4] = {a4.x, a4.y, a4.z, a4.w};
            float bb[4] = {b4.x, b4.y, b4.z, b4.w};
#pragma unroll
            for (int mi = 0; mi < 4; mi++)
#pragma unroll
                for (int ni = 0; ni < 4; ni++) acc[mi][ni] += a[mi] * bb[ni];
        }
    }

#pragma unroll
    for (int mi = 0; mi < 4; mi++) {
        int r = row0 + m0 + mi;
        int tt = r >> 8;        // r / B
        int b  = r & 255;       // r % B
#pragma unroll
        for (int ni = 0; ni < 4; ni++) {
            int n = n0 + ni;
            out[((size_t)b * S + tt) * OUT + n] = acc[mi][ni] + b2[n];
        }
    }
}

// ---------------- launch ----------------
extern "C" void kernel_launch(void* const* d_in, const int* in_sizes, int n_in,
                              void* d_out, int out_size)
{
    const float* x   = (const float*)d_in[0];
    const float* Wih = (const float*)d_in[1];
    const float* bih = (const float*)d_in[2];
    const float* Whh = (const float*)d_in[3];
    const float* bhh = (const float*)d_in[4];
    const float* Wd  = (const float*)d_in[5];
    const float* bd  = (const float*)d_in[6];
    const float* W2  = (const float*)d_in[7];
    const float* b2  = (const float*)d_in[8];
    float* out = (float*)d_out;

    zero_kernel<<<512, 256>>>();

    dim3 sg(B / 64, H / 16);   // (4, 64) = 256 blocks
    for (int t = 0; t < S; t++) {
        lstm_step<<<sg, 256>>>(x, Wih, bih, Whh, bhh, t);
    }

    dense1<<<(S * B) / 128, 256>>>(Wd, bd);
    dense2<<<(S * B) / 64, 256>>>(W2, b2, out);
}

// round 5
// speedup vs baseline: 2.2017x; 2.2017x over previous
#include <cuda_runtime.h>
#include <cuda_bf16.h>
#include <math.h>
#include <stdint.h>

#define B_   256
#define S_   512
#define IN_  64
#define H_   1024
#define G4   4096          // 4*H
#define KTOT 1088          // IN + H
#define HEAD_ 128
#define OUT_ 64
#define KC   64            // K elements per SMEM chunk (bf16, 128B rows)
#define NCHUNK 17          // 1088/64

// Arch-specific (a-suffix) feature gate: tcgen05 only exists on sm_100a/sm_103a
// targets, NOT on the family/forward-compat compute_103 pass the harness also builds.
#if defined(__CUDA_ARCH_FEAT_SM103_ALL) || defined(__CUDA_ARCH_FEAT_SM100_ALL) || \
    (defined(__CUDA_ARCH_SPECIFIC__) && (__CUDA_ARCH_SPECIFIC__ >= 1000))
#define HAS_TCGEN05 1
#else
#define HAS_TCGEN05 0
#endif

// ---------------- device scratch ----------------
__device__ float g_c[B_ * H_];
__device__ float g_hall[(size_t)S_ * B_ * H_];    // fp32 h for dense head
__device__ float g_P[(size_t)S_ * B_ * HEAD_];
__device__ __nv_bfloat16 g_Wc_hi[(size_t)G4 * KTOT];   // [4096][1088] = [Wih|Whh] rows
__device__ __nv_bfloat16 g_Wc_lo[(size_t)G4 * KTOT];
__device__ __nv_bfloat16 g_x_hi[(size_t)S_ * B_ * IN_]; // [t][b][in]
__device__ __nv_bfloat16 g_x_lo[(size_t)S_ * B_ * IN_];
__device__ __nv_bfloat16 g_h_hi[2][B_ * H_];
__device__ __nv_bfloat16 g_h_lo[2][B_ * H_];

__device__ __forceinline__ float sigf(float x) { return 1.0f / (1.0f + expf(-x)); }

// ---------------- PTX helpers (only referenced inside HAS_TCGEN05 region) ----------------
__device__ __forceinline__ uint32_t smem_u32(const void* p) {
    return (uint32_t)__cvta_generic_to_shared(p);
}
#if HAS_TCGEN05
__device__ __forceinline__ uint64_t make_desc_sw128(uint32_t addr) {
    // layout=SW128(2)<<61 | version=1<<46 | SBO=64<<32 | LBO=1<<16
    return 0x4000404000010000ULL | (uint64_t)((addr >> 4) & 0x3FFF);
}
__device__ __forceinline__ void mbar_init(uint32_t mbar, uint32_t cnt) {
    asm volatile("mbarrier.init.shared.b64 [%0], %1;" :: "r"(mbar), "r"(cnt) : "memory");
}
__device__ __forceinline__ void mbar_inval(uint32_t mbar) {
    asm volatile("mbarrier.inval.shared.b64 [%0];" :: "r"(mbar) : "memory");
}
__device__ __forceinline__ void mbar_wait(uint32_t mbar, uint32_t parity) {
    asm volatile(
        "{\n\t.reg .pred P1;\n\t"
        "WAIT_LOOP_%=:\n\t"
        "mbarrier.try_wait.parity.acquire.cta.shared::cta.b64 P1, [%0], %1, 0x989680;\n\t"
        "@P1 bra.uni WAIT_DONE_%=;\n\t"
        "bra.uni WAIT_LOOP_%=;\n\t"
        "WAIT_DONE_%=:\n\t}"
        :: "r"(mbar), "r"(parity) : "memory");
}
__device__ __forceinline__ void tmem_alloc(uint32_t smem_res, uint32_t ncols) {
    asm volatile("tcgen05.alloc.cta_group::1.sync.aligned.shared::cta.b32 [%0], %1;"
                 :: "r"(smem_res), "r"(ncols) : "memory");
}
__device__ __forceinline__ void tmem_dealloc(uint32_t tmem, uint32_t ncols) {
    asm volatile("tcgen05.dealloc.cta_group::1.sync.aligned.b32 %0, %1;" :: "r"(tmem), "r"(ncols));
}
__device__ __forceinline__ void tmem_relinquish() {
    asm volatile("tcgen05.relinquish_alloc_permit.cta_group::1.sync.aligned;");
}
__device__ __forceinline__ void tc_commit(uint32_t mbar) {
    asm volatile("tcgen05.commit.cta_group::1.mbarrier::arrive::one.shared::cluster.b64 [%0];"
                 :: "r"(mbar) : "memory");
}
__device__ __forceinline__ void tc_fence_after() {
    asm volatile("tcgen05.fence::after_thread_sync;" ::: "memory");
}
__device__ __forceinline__ void tc_fence_before() {
    asm volatile("tcgen05.fence::before_thread_sync;" ::: "memory");
}
__device__ __forceinline__ void tc_wait_ld() {
    asm volatile("tcgen05.wait::ld.sync.aligned;" ::: "memory");
}
__device__ __forceinline__ void fence_proxy_async_shared() {
    asm volatile("fence.proxy.async.shared::cta;" ::: "memory");
}
// SS cg1 kind::f16 MMA (bf16 inputs via idesc, fp32 accum)
__device__ __forceinline__ void mma_f16_ss(uint32_t d_tmem, uint64_t a_desc, uint64_t b_desc,
                                           uint32_t idesc, uint32_t enable) {
    asm volatile(
        "{\n\t.reg .pred p;\n\t"
        "setp.ne.u32 p, %4, 0;\n\t"
        "tcgen05.mma.cta_group::1.kind::f16 [%0], %1, %2, %3, {%5, %5, %5, %5}, p;\n\t}"
        :: "r"(d_tmem), "l"(a_desc), "l"(b_desc), "r"(idesc), "r"(enable), "r"(0u)
        : "memory");
}
#define TC_LD_X32(r, tmem_addr) \
    asm volatile( \
        "tcgen05.ld.sync.aligned.32x32b.x32.b32 " \
        "{%0, %1, %2, %3, %4, %5, %6, %7, " \
        " %8, %9, %10, %11, %12, %13, %14, %15, " \
        " %16, %17, %18, %19, %20, %21, %22, %23, " \
        " %24, %25, %26, %27, %28, %29, %30, %31}, [%32];" \
        : "=r"((r)[0]),  "=r"((r)[1]),  "=r"((r)[2]),  "=r"((r)[3]), \
          "=r"((r)[4]),  "=r"((r)[5]),  "=r"((r)[6]),  "=r"((r)[7]), \
          "=r"((r)[8]),  "=r"((r)[9]),  "=r"((r)[10]), "=r"((r)[11]), \
          "=r"((r)[12]), "=r"((r)[13]), "=r"((r)[14]), "=r"((r)[15]), \
          "=r"((r)[16]), "=r"((r)[17]), "=r"((r)[18]), "=r"((r)[19]), \
          "=r"((r)[20]), "=r"((r)[21]), "=r"((r)[22]), "=r"((r)[23]), \
          "=r"((r)[24]), "=r"((r)[25]), "=r"((r)[26]), "=r"((r)[27]), \
          "=r"((r)[28]), "=r"((r)[29]), "=r"((r)[30]), "=r"((r)[31]) \
        : "r"(tmem_addr))
#endif  // HAS_TCGEN05

// idesc: F32 accum | BF16 a | BF16 b | N=64 | M=128
#define IDESC ((1u << 4) | (1u << 7) | (1u << 10) | (8u << 17) | (8u << 24))

// SMEM layout (dynamic): [0]=tmem ptr, [8],[16]=mbarriers, stages at 1024
#define STAGE_BYTES 49152
#define OFF_A_HI 0
#define OFF_A_LO 16384
#define OFF_B_HI 32768
#define OFF_B_LO 40960
#define SMEM_TOTAL (1024 + 2 * STAGE_BYTES)

// ---------------- prep kernels ----------------
__global__ void prep_state() {
    const int n = B_ * H_;
    for (int i = blockIdx.x * blockDim.x + threadIdx.x; i < n; i += gridDim.x * blockDim.x) {
        g_c[i] = 0.f;
        g_h_hi[0][i] = __float2bfloat16(0.f);
        g_h_lo[0][i] = __float2bfloat16(0.f);
    }
}
__global__ void prep_w(const float* __restrict__ Wih, const float* __restrict__ Whh) {
    const size_t n = (size_t)G4 * KTOT;
    for (size_t i = blockIdx.x * blockDim.x + threadIdx.x; i < n; i += (size_t)gridDim.x * blockDim.x) {
        int r = (int)(i / KTOT);
        int k = (int)(i - (size_t)r * KTOT);
        float v = (k < IN_) ? Wih[(size_t)r * IN_ + k] : Whh[(size_t)r * H_ + (k - IN_)];
        __nv_bfloat16 hi = __float2bfloat16(v);
        g_Wc_hi[i] = hi;
        g_Wc_lo[i] = __float2bfloat16(v - __bfloat162float(hi));
    }
}
__global__ void prep_x(const float* __restrict__ x) {
    const size_t n = (size_t)S_ * B_ * IN_;
    for (size_t i = blockIdx.x * blockDim.x + threadIdx.x; i < n; i += (size_t)gridDim.x * blockDim.x) {
        int t = (int)(i / (B_ * IN_));
        int rem = (int)(i - (size_t)t * (B_ * IN_));
        int b = rem / IN_;
        int ii = rem - b * IN_;
        float v = x[((size_t)b * S_ + t) * IN_ + ii];
        __nv_bfloat16 hi = __float2bfloat16(v);
        g_x_hi[i] = hi;
        g_x_lo[i] = __float2bfloat16(v - __bfloat162float(hi));
    }
}

// ---------------- tcgen05 LSTM step ----------------
// Grid: (2, 64). blockIdx.x -> M tile (128 batch rows), blockIdx.y -> 16 hidden units
// (N tile of 64 = 4 gates x 16 units). 256 threads.
__global__ void __launch_bounds__(256, 1) lstm_step_tc(
    const float* __restrict__ bih, const float* __restrict__ bhh, int t)
{
#if HAS_TCGEN05
    extern __shared__ char smem[];
    const uint32_t sb = smem_u32(smem);
    const int tid = threadIdx.x;
    const int wid = tid >> 5;
    const int lane = tid & 31;
    const int bm0 = blockIdx.x * 128;
    const int j0 = blockIdx.y * 16;
    const int cur = t & 1, nxt = cur ^ 1;

    // TMEM alloc (warp 0, collective). D uses cols 0..63.
    if (wid == 0) {
        tmem_alloc(sb, 128);
        tmem_relinquish();
    }
    if (tid == 0) {
        mbar_init(sb + 8, 1);
        mbar_init(sb + 16, 1);
    }
    __syncthreads();
    const uint32_t tmem = *(const uint32_t*)smem;

    uint32_t ph0 = 0, ph1 = 0;

    for (int ck = 0; ck < NCHUNK; ck++) {
        const int buf = ck & 1;
        const uint32_t stage = sb + 1024 + buf * STAGE_BYTES;
        char* stage_g = smem + 1024 + buf * STAGE_BYTES;

        // ---- prefetch global loads into registers ----
        uint4 ra_hi[4], ra_lo[4];
        int arow[4], acol[4];
#pragma unroll
        for (int q = 0; q < 4; q++) {
            int idx = tid + q * 256;
            arow[q] = idx >> 3;
            acol[q] = idx & 7;
            const __nv_bfloat16 *ph, *pl;
            if (ck == 0) {
                size_t o = ((size_t)t * B_ + bm0 + arow[q]) * IN_ + acol[q] * 8;
                ph = g_x_hi + o; pl = g_x_lo + o;
            } else {
                size_t o = (size_t)(bm0 + arow[q]) * H_ + (ck - 1) * KC + acol[q] * 8;
                ph = g_h_hi[cur] + o; pl = g_h_lo[cur] + o;
            }
            ra_hi[q] = *(const uint4*)ph;
            ra_lo[q] = *(const uint4*)pl;
        }
        uint4 rb_hi[2], rb_lo[2];
        int brow[2], bcol[2];
#pragma unroll
        for (int q = 0; q < 2; q++) {
            int idx = tid + q * 256;
            brow[q] = idx >> 3;
            bcol[q] = idx & 7;
            int grow = ((brow[q] >> 4) << 10) + j0 + (brow[q] & 15);
            size_t o = (size_t)grow * KTOT + ck * KC + bcol[q] * 8;
            rb_hi[q] = *(const uint4*)(g_Wc_hi + o);
            rb_lo[q] = *(const uint4*)(g_Wc_lo + o);
        }

        // ---- wait for MMA that used this buffer two chunks ago ----
        if (ck >= 2) {
            if (buf == 0) { mbar_wait(sb + 8, ph0); ph0 ^= 1; }
            else          { mbar_wait(sb + 16, ph1); ph1 ^= 1; }
        }

        // ---- STS with SW128 swizzle ----
#pragma unroll
        for (int q = 0; q < 4; q++) {
            uint32_t off = arow[q] * 128 + acol[q] * 16;
            uint32_t sw = off ^ ((off >> 3) & 0x70);
            *(uint4*)(stage_g + OFF_A_HI + sw) = ra_hi[q];
            *(uint4*)(stage_g + OFF_A_LO + sw) = ra_lo[q];
        }
#pragma unroll
        for (int q = 0; q < 2; q++) {
            uint32_t off = brow[q] * 128 + bcol[q] * 16;
            uint32_t sw = off ^ ((off >> 3) & 0x70);
            *(uint4*)(stage_g + OFF_B_HI + sw) = rb_hi[q];
            *(uint4*)(stage_g + OFF_B_LO + sw) = rb_lo[q];
        }
        __syncthreads();

        // ---- issue 12 MMAs (3 split terms x 4 K-steps) ----
        if (tid == 0) {
            fence_proxy_async_shared();
            uint64_t dAh = make_desc_sw128(stage + OFF_A_HI);
            uint64_t dAl = make_desc_sw128(stage + OFF_A_LO);
            uint64_t dBh = make_desc_sw128(stage + OFF_B_HI);
            uint64_t dBl = make_desc_sw128(stage + OFF_B_LO);
#pragma unroll
            for (int k4 = 0; k4 < 4; k4++) {
                uint32_t en0 = (ck > 0 || k4 > 0) ? 1u : 0u;
                mma_f16_ss(tmem, dAh + k4 * 2, dBh + k4 * 2, IDESC, en0);
                mma_f16_ss(tmem, dAh + k4 * 2, dBl + k4 * 2, IDESC, 1u);
                mma_f16_ss(tmem, dAl + k4 * 2, dBh + k4 * 2, IDESC, 1u);
            }
            tc_commit(buf == 0 ? sb + 8 : sb + 16);
        }
        // no extra sync: next iteration's buffer-overwrite is gated by mbar_wait
    }

    // ---- final wait + fused LSTM epilogue ----
    {
        const int lastbuf = (NCHUNK - 1) & 1;  // 0
        if (lastbuf == 0) mbar_wait(sb + 8, ph0);
        else              mbar_wait(sb + 16, ph1);
    }
    tc_fence_after();

    if (wid < 4) {
        uint32_t r[64];
        TC_LD_X32(r, tmem);
        TC_LD_X32(r + 32, tmem + 32);
        tc_wait_ld();
        tc_fence_before();

        const int brow_g = bm0 + wid * 32 + lane;   // batch row
        const int cbase = brow_g * H_ + j0;
#pragma unroll
        for (int u = 0; u < 16; u++) {
            float ig = __uint_as_float(r[u])      + bih[j0 + u]          + bhh[j0 + u];
            float fg = __uint_as_float(r[16 + u]) + bih[H_ + j0 + u]     + bhh[H_ + j0 + u];
            float gg = __uint_as_float(r[32 + u]) + bih[2 * H_ + j0 + u] + bhh[2 * H_ + j0 + u];
            float og = __uint_as_float(r[48 + u]) + bih[3 * H_ + j0 + u] + bhh[3 * H_ + j0 + u];
            float c_old = g_c[cbase + u];
            float cn = sigf(fg) * c_old + sigf(ig) * tanhf(gg);
            float hn = sigf(og) * tanhf(cn);
            g_c[cbase + u] = cn;
            g_hall[(size_t)t * (B_ * H_) + cbase + u] = hn;
            __nv_bfloat16 hh = __float2bfloat16(hn);
            g_h_hi[nxt][cbase + u] = hh;
            g_h_lo[nxt][cbase + u] = __float2bfloat16(hn - __bfloat162float(hh));
        }
    }
    __syncthreads();
    if (tid == 0) { mbar_inval(sb + 8); mbar_inval(sb + 16); }
    __syncthreads();
    if (wid == 0) tmem_dealloc(tmem, 128);
#else
    // ---- correct (slow) SIMT fallback for the non-'a' compilation pass ----
    // Never executes on GB300 (driver picks the exact-match sm_103a cubin),
    // but must be correct if it ever does.
    const int tid = threadIdx.x;
    const int bm0 = blockIdx.x * 128;
    const int j0 = blockIdx.y * 16;
    const int cur = t & 1, nxt = cur ^ 1;
    for (int o = tid; o < 128 * 16; o += 256) {
        int row = o >> 4;
        int u = o & 15;
        int b = bm0 + row;
        int jg = j0 + u;
        float acc[4] = {0.f, 0.f, 0.f, 0.f};
        for (int k = 0; k < KTOT; k++) {
            float a;
            if (k < IN_) {
                size_t xo = ((size_t)t * B_ + b) * IN_ + k;
                a = __bfloat162float(g_x_hi[xo]) + __bfloat162float(g_x_lo[xo]);
            } else {
                size_t ho = (size_t)b * H_ + (k - IN_);
                a = __bfloat162float(g_h_hi[cur][ho]) + __bfloat162float(g_h_lo[cur][ho]);
            }
#pragma unroll
            for (int g = 0; g < 4; g++) {
                size_t wi = (size_t)(g * H_ + jg) * KTOT + k;
                acc[g] += a * (__bfloat162float(g_Wc_hi[wi]) + __bfloat162float(g_Wc_lo[wi]));
            }
        }
        float ig = acc[0] + bih[jg] + bhh[jg];
        float fg = acc[1] + bih[H_ + jg] + bhh[H_ + jg];
        float gg = acc[2] + bih[2 * H_ + jg] + bhh[2 * H_ + jg];
        float og = acc[3] + bih[3 * H_ + jg] + bhh[3 * H_ + jg];
        int idx = b * H_ + jg;
        float c_old = g_c[idx];
        float cn = sigf(fg) * c_old + sigf(ig) * tanhf(gg);
        float hn = sigf(og) * tanhf(cn);
        g_c[idx] = cn;
        g_hall[(size_t)t * (B_ * H_) + idx] = hn;
        __nv_bfloat16 hh = __float2bfloat16(hn);
        g_h_hi[nxt][idx] = hh;
        g_h_lo[nxt][idx] = __float2bfloat16(hn - __bfloat162float(hh));
    }
#endif
}

// ---------------- dense1: P = relu(h_all @ Wd^T + bd) ----------------
__global__ __launch_bounds__(256) void dense1(
    const float* __restrict__ Wd, const float* __restrict__ bd)
{
    __shared__ float As[8][132];
    __shared__ float Bs[8][132];
    const int tid = threadIdx.x;
    const int row0 = blockIdx.x * 128;
    const int lm = tid >> 1;
    const int lk = (tid & 1) << 2;
    const int m0 = (tid >> 4) << 3;
    const int n0 = (tid & 15) << 3;

    float acc[8][8];
#pragma unroll
    for (int i = 0; i < 8; i++)
#pragma unroll
        for (int j = 0; j < 8; j++) acc[i][j] = 0.f;

    for (int kk = 0; kk < H_; kk += 8) {
        float4 av = *(const float4*)(g_hall + (size_t)(row0 + lm) * H_ + kk + lk);
        float4 bv = *(const float4*)(Wd + (size_t)lm * H_ + kk + lk);
        __syncthreads();
        As[lk + 0][lm] = av.x; As[lk + 1][lm] = av.y;
        As[lk + 2][lm] = av.z; As[lk + 3][lm] = av.w;
        Bs[lk + 0][lm] = bv.x; Bs[lk + 1][lm] = bv.y;
        Bs[lk + 2][lm] = bv.z; Bs[lk + 3][lm] = bv.w;
        __syncthreads();
#pragma unroll
        for (int k = 0; k < 8; k++) {
            float4 a0 = *(const float4*)&As[k][m0];
            float4 a1 = *(const float4*)&As[k][m0 + 4];
            float4 b0 = *(const float4*)&Bs[k][n0];
            float4 b1 = *(const float4*)&Bs[k][n0 + 4];
            float a[8] = {a0.x, a0.y, a0.z, a0.w, a1.x, a1.y, a1.z, a1.w};
            float bb[8] = {b0.x, b0.y, b0.z, b0.w, b1.x, b1.y, b1.z, b1.w};
#pragma unroll
            for (int mi = 0; mi < 8; mi++)
#pragma unroll
                for (int ni = 0; ni < 8; ni++) acc[mi][ni] += a[mi] * bb[ni];
        }
    }
#pragma unroll
    for (int mi = 0; mi < 8; mi++) {
        size_t r = (size_t)(row0 + m0 + mi);
#pragma unroll
        for (int ni = 0; ni < 8; ni++) {
            int n = n0 + ni;
            float v = acc[mi][ni] + bd[n];
            g_P[r * HEAD_ + n] = v > 0.f ? v : 0.f;
        }
    }
}

// ---------------- dense2: out = P @ W2^T + b2 ----------------
__global__ __launch_bounds__(256) void dense2(
    const float* __restrict__ W2, const float* __restrict__ b2,
    float* __restrict__ out)
{
    __shared__ float As[16][68];
    __shared__ float Bs[16][68];
    const int tid = threadIdx.x;
    const int row0 = blockIdx.x * 64;
    const int lm = tid >> 2;
    const int lk = (tid & 3) << 2;
    const int m0 = (tid >> 4) << 2;
    const int n0 = (tid & 15) << 2;

    float acc[4][4];
#pragma unroll
    for (int i = 0; i < 4; i++)
#pragma unroll
        for (int j = 0; j < 4; j++) acc[i][j] = 0.f;

    for (int kk = 0; kk < HEAD_; kk += 16) {
        float4 av = *(const float4*)(g_P + (size_t)(row0 + lm) * HEAD_ + kk + lk);
        float4 bv = *(const float4*)(W2 + (size_t)lm * HEAD_ + kk + lk);
        __syncthreads();
        As[lk + 0][lm] = av.x; As[lk + 1][lm] = av.y;
        As[lk + 2][lm] = av.z; As[lk + 3][lm] = av.w;
        Bs[lk + 0][lm] = bv.x; Bs[lk + 1][lm] = bv.y;
        Bs[lk + 2][lm] = bv.z; Bs[lk + 3][lm] = bv.w;
        __syncthreads();
#pragma unroll
        for (int k = 0; k < 16; k++) {
            float4 a4 = *(const float4*)&As[k][m0];
            float4 b4 = *(const float4*)&Bs[k][n0];
            float a[4] = {a4.x, a4.y, a4.z, a4.w};
            float bb[4] = {b4.x, b4.y, b4.z, b4.w};
#pragma unroll
            for (int mi = 0; mi < 4; mi++)
#pragma unroll
                for (int ni = 0; ni < 4; ni++) acc[mi][ni] += a[mi] * bb[ni];
        }
    }
#pragma unroll
    for (int mi = 0; mi < 4; mi++) {
        int r = row0 + m0 + mi;
        int tt = r >> 8;
        int b = r & 255;
#pragma unroll
        for (int ni = 0; ni < 4; ni++) {
            int n = n0 + ni;
            out[((size_t)b * S_ + tt) * OUT_ + n] = acc[mi][ni] + b2[n];
        }
    }
}

// ---------------- launch ----------------
extern "C" void kernel_launch(void* const* d_in, const int* in_sizes, int n_in,
                              void* d_out, int out_size)
{
    const float* x   = (const float*)d_in[0];
    const float* Wih = (const float*)d_in[1];
    const float* bih = (const float*)d_in[2];
    const float* Whh = (const float*)d_in[3];
    const float* bhh = (const float*)d_in[4];
    const float* Wd  = (const float*)d_in[5];
    const float* bd  = (const float*)d_in[6];
    const float* W2  = (const float*)d_in[7];
    const float* b2  = (const float*)d_in[8];
    float* out = (float*)d_out;

    cudaFuncSetAttribute(lstm_step_tc, cudaFuncAttributeMaxDynamicSharedMemorySize, SMEM_TOTAL);

    prep_state<<<256, 256>>>();
    prep_w<<<512, 256>>>(Wih, Whh);
    prep_x<<<512, 256>>>(x);

    dim3 sg(2, 64);  // 128 CTAs
    for (int t = 0; t < S_; t++) {
        lstm_step_tc<<<sg, 256, SMEM_TOTAL>>>(bih, bhh, t);
    }

    dense1<<<(S_ * B_) / 128, 256>>>(Wd, bd);
    dense2<<<(S_ * B_) / 64, 256>>>(W2, b2, out);
}

// round 6
// speedup vs baseline: 3.3567x; 1.5246x over previous
#include <cuda_runtime.h>
#include <cuda_bf16.h>
#include <math.h>
#include <stdint.h>

#define B_   256
#define S_   512
#define IN_  64
#define H_   1024
#define G4   4096          // 4*H
#define KTOT 1088          // IN + H
#define HEAD_ 128
#define OUT_ 64
#define KC   64            // K elements per SMEM chunk (bf16, 128B rows)
#define NCHUNK 17          // 1088/64
#define NTILE 128          // N per CTA: 32 hidden units x 4 gates
#define UNITS 32           // hidden units per CTA

// Arch-specific (a-suffix) feature gate: tcgen05 only exists on sm_100a/sm_103a
// targets, NOT on the family/forward-compat compute_103 pass the harness also builds.
#if defined(__CUDA_ARCH_FEAT_SM103_ALL) || defined(__CUDA_ARCH_FEAT_SM100_ALL) || \
    (defined(__CUDA_ARCH_SPECIFIC__) && (__CUDA_ARCH_SPECIFIC__ >= 1000))
#define HAS_TCGEN05 1
#else
#define HAS_TCGEN05 0
#endif

// ---------------- device scratch ----------------
__device__ float g_c[B_ * H_];
__device__ float g_hall[(size_t)S_ * B_ * H_];    // fp32 h for dense head
__device__ float g_P[(size_t)S_ * B_ * HEAD_];
__device__ __nv_bfloat16 g_Wc_hi[(size_t)G4 * KTOT];   // [4096][1088] = [Wih|Whh] rows
__device__ __nv_bfloat16 g_Wc_lo[(size_t)G4 * KTOT];
__device__ __nv_bfloat16 g_x_hi[(size_t)S_ * B_ * IN_]; // [t][b][in]
__device__ __nv_bfloat16 g_x_lo[(size_t)S_ * B_ * IN_];
__device__ __nv_bfloat16 g_h_hi[2][B_ * H_];
__device__ __nv_bfloat16 g_h_lo[2][B_ * H_];

__device__ __forceinline__ float sigf(float x) { return 1.0f / (1.0f + expf(-x)); }

__device__ __forceinline__ uint32_t smem_u32(const void* p) {
    return (uint32_t)__cvta_generic_to_shared(p);
}

#if HAS_TCGEN05
__device__ __forceinline__ uint64_t make_desc_sw128(uint32_t addr) {
    // layout=SW128(2)<<61 | version=1<<46 | SBO=64<<32 | LBO=1<<16
    return 0x4000404000010000ULL | (uint64_t)((addr >> 4) & 0x3FFF);
}
__device__ __forceinline__ void mbar_init(uint32_t mbar, uint32_t cnt) {
    asm volatile("mbarrier.init.shared.b64 [%0], %1;" :: "r"(mbar), "r"(cnt) : "memory");
}
__device__ __forceinline__ void mbar_inval(uint32_t mbar) {
    asm volatile("mbarrier.inval.shared.b64 [%0];" :: "r"(mbar) : "memory");
}
__device__ __forceinline__ void mbar_wait(uint32_t mbar, uint32_t parity) {
    asm volatile(
        "{\n\t.reg .pred P1;\n\t"
        "WAIT_LOOP_%=:\n\t"
        "mbarrier.try_wait.parity.acquire.cta.shared::cta.b64 P1, [%0], %1, 0x989680;\n\t"
        "@P1 bra.uni WAIT_DONE_%=;\n\t"
        "bra.uni WAIT_LOOP_%=;\n\t"
        "WAIT_DONE_%=:\n\t}"
        :: "r"(mbar), "r"(parity) : "memory");
}
__device__ __forceinline__ void tmem_alloc(uint32_t smem_res, uint32_t ncols) {
    asm volatile("tcgen05.alloc.cta_group::1.sync.aligned.shared::cta.b32 [%0], %1;"
                 :: "r"(smem_res), "r"(ncols) : "memory");
}
__device__ __forceinline__ void tmem_dealloc(uint32_t tmem, uint32_t ncols) {
    asm volatile("tcgen05.dealloc.cta_group::1.sync.aligned.b32 %0, %1;" :: "r"(tmem), "r"(ncols));
}
__device__ __forceinline__ void tmem_relinquish() {
    asm volatile("tcgen05.relinquish_alloc_permit.cta_group::1.sync.aligned;");
}
__device__ __forceinline__ void tc_commit(uint32_t mbar) {
    asm volatile("tcgen05.commit.cta_group::1.mbarrier::arrive::one.shared::cluster.b64 [%0];"
                 :: "r"(mbar) : "memory");
}
__device__ __forceinline__ void tc_fence_after() {
    asm volatile("tcgen05.fence::after_thread_sync;" ::: "memory");
}
__device__ __forceinline__ void tc_fence_before() {
    asm volatile("tcgen05.fence::before_thread_sync;" ::: "memory");
}
__device__ __forceinline__ void tc_wait_ld() {
    asm volatile("tcgen05.wait::ld.sync.aligned;" ::: "memory");
}
__device__ __forceinline__ void fence_proxy_async_shared() {
    asm volatile("fence.proxy.async.shared::cta;" ::: "memory");
}
__device__ __forceinline__ void mma_f16_ss(uint32_t d_tmem, uint64_t a_desc, uint64_t b_desc,
                                           uint32_t idesc, uint32_t enable) {
    asm volatile(
        "{\n\t.reg .pred p;\n\t"
        "setp.ne.u32 p, %4, 0;\n\t"
        "tcgen05.mma.cta_group::1.kind::f16 [%0], %1, %2, %3, {%5, %5, %5, %5}, p;\n\t}"
        :: "r"(d_tmem), "l"(a_desc), "l"(b_desc), "r"(idesc), "r"(enable), "r"(0u)
        : "memory");
}
__device__ __forceinline__ void cp16(uint32_t dst, const void* src) {
    asm volatile("cp.async.cg.shared.global [%0], [%1], 16;" :: "r"(dst), "l"(src));
}
__device__ __forceinline__ void cp_commit() {
    asm volatile("cp.async.commit_group;" ::: "memory");
}
#define TC_LD_X16(r, tmem_addr) \
    asm volatile( \
        "tcgen05.ld.sync.aligned.32x32b.x16.b32 " \
        "{%0, %1, %2, %3, %4, %5, %6, %7, " \
        " %8, %9, %10, %11, %12, %13, %14, %15}, [%16];" \
        : "=r"((r)[0]),  "=r"((r)[1]),  "=r"((r)[2]),  "=r"((r)[3]), \
          "=r"((r)[4]),  "=r"((r)[5]),  "=r"((r)[6]),  "=r"((r)[7]), \
          "=r"((r)[8]),  "=r"((r)[9]),  "=r"((r)[10]), "=r"((r)[11]), \
          "=r"((r)[12]), "=r"((r)[13]), "=r"((r)[14]), "=r"((r)[15]) \
        : "r"(tmem_addr))
#endif  // HAS_TCGEN05

// idesc: F32 accum | BF16 a | BF16 b | N=128 | M=128
#define IDESC ((1u << 4) | (1u << 7) | (1u << 10) | (16u << 17) | (8u << 24))

// SMEM layout: [0]=tmem ptr, [8/16/24]=mbarriers, [256..768)=bias, stages at 1024
#define STAGE_BYTES 65536
#define OFF_A_HI 0
#define OFF_A_LO 16384
#define OFF_B_HI 32768
#define OFF_B_LO 49152
#define NSTAGE 3
#define SMEM_TOTAL (1024 + NSTAGE * STAGE_BYTES)

// ---------------- prep kernels ----------------
__global__ void prep_state() {
    const int n = B_ * H_;
    for (int i = blockIdx.x * blockDim.x + threadIdx.x; i < n; i += gridDim.x * blockDim.x) {
        g_c[i] = 0.f;
        g_h_hi[0][i] = __float2bfloat16(0.f);
        g_h_lo[0][i] = __float2bfloat16(0.f);
    }
}
__global__ void prep_w(const float* __restrict__ Wih, const float* __restrict__ Whh) {
    const size_t n = (size_t)G4 * KTOT;
    for (size_t i = blockIdx.x * blockDim.x + threadIdx.x; i < n; i += (size_t)gridDim.x * blockDim.x) {
        int r = (int)(i / KTOT);
        int k = (int)(i - (size_t)r * KTOT);
        float v = (k < IN_) ? Wih[(size_t)r * IN_ + k] : Whh[(size_t)r * H_ + (k - IN_)];
        __nv_bfloat16 hi = __float2bfloat16(v);
        g_Wc_hi[i] = hi;
        g_Wc_lo[i] = __float2bfloat16(v - __bfloat162float(hi));
    }
}
__global__ void prep_x(const float* __restrict__ x) {
    const size_t n = (size_t)S_ * B_ * IN_;
    for (size_t i = blockIdx.x * blockDim.x + threadIdx.x; i < n; i += (size_t)gridDim.x * blockDim.x) {
        int t = (int)(i / (B_ * IN_));
        int rem = (int)(i - (size_t)t * (B_ * IN_));
        int b = rem / IN_;
        int ii = rem - b * IN_;
        float v = x[((size_t)b * S_ + t) * IN_ + ii];
        __nv_bfloat16 hi = __float2bfloat16(v);
        g_x_hi[i] = hi;
        g_x_lo[i] = __float2bfloat16(v - __bfloat162float(hi));
    }
}

// ---------------- tcgen05 LSTM step ----------------
// Grid (2, 32): blockIdx.x -> M tile (128 batch rows), blockIdx.y -> 32 hidden units
// (N tile of 128 = 4 gates x 32 units). 256 threads. 3-stage cp.async pipeline.
__global__ void __launch_bounds__(256, 1) lstm_step_tc(
    const float* __restrict__ bih, const float* __restrict__ bhh, int t)
{
#if HAS_TCGEN05
    extern __shared__ char smem[];
    const uint32_t sb = smem_u32(smem);
    const int tid = threadIdx.x;
    const int wid = tid >> 5;
    const int lane = tid & 31;
    const int bm0 = blockIdx.x * 128;
    const int j0 = blockIdx.y * UNITS;
    const int cur = t & 1, nxt = cur ^ 1;

    // TMEM alloc (warp 0, collective). D uses cols 0..127.
    if (wid == 0) {
        tmem_alloc(sb, 128);
        tmem_relinquish();
    }
    if (tid == 0) {
        mbar_init(sb + 8, 1);
        mbar_init(sb + 16, 1);
        mbar_init(sb + 24, 1);
    }
    // biases -> smem: bsum[c] for B-row c (gate = c>>5, unit = c&31)
    if (tid < NTILE) {
        int grow = ((tid >> 5) << 10) + j0 + (tid & 31);
        ((float*)(smem + 256))[tid] = bih[grow] + bhh[grow];
    }
    __syncthreads();
    const uint32_t tmem = *(const uint32_t*)smem;

    // chunk loader: 16 cp.async of 16B per thread (A hi/lo 128x64, B hi/lo 128x64)
    auto load_chunk = [&](int cn, int buf) {
        const uint32_t stage_s = sb + 1024 + buf * STAGE_BYTES;
#pragma unroll
        for (int q = 0; q < 4; q++) {
            int slot = tid + q * 256;
            int row = slot >> 3, c16 = slot & 7;
            uint32_t off = row * 128 + c16 * 16;
            uint32_t sw = off ^ ((off >> 3) & 0x70);
            const __nv_bfloat16 *ah, *al;
            if (cn == 0) {
                size_t o = ((size_t)t * B_ + bm0 + row) * IN_ + c16 * 8;
                ah = g_x_hi + o; al = g_x_lo + o;
            } else {
                size_t o = (size_t)(bm0 + row) * H_ + (cn - 1) * KC + c16 * 8;
                ah = g_h_hi[cur] + o; al = g_h_lo[cur] + o;
            }
            cp16(stage_s + OFF_A_HI + sw, ah);
            cp16(stage_s + OFF_A_LO + sw, al);
            int grow = ((row >> 5) << 10) + j0 + (row & 31);
            size_t ob = (size_t)grow * KTOT + cn * KC + c16 * 8;
            cp16(stage_s + OFF_B_HI + sw, g_Wc_hi + ob);
            cp16(stage_s + OFF_B_LO + sw, g_Wc_lo + ob);
        }
        cp_commit();
    };

    // prologue: chunks 0,1 in flight
    load_chunk(0, 0);
    load_chunk(1, 1);

#pragma unroll
    for (int ck = 0; ck < NCHUNK; ck++) {
        // prefetch chunk ck+2 (buffer reuse gated by MMA of chunk ck-1)
        const int cn = ck + 2;
        if (cn <= NCHUNK - 1) {
            const int b = cn % NSTAGE;
            if (cn >= NSTAGE) {
                // wait for MMA of chunk cn-3 on mbar[b]; compile-time parity
                mbar_wait(sb + 8 + 8 * b, (uint32_t)(((cn - NSTAGE - b) / NSTAGE) & 1));
            }
            load_chunk(cn, b);
        }
        // wait for chunk ck's cp.async data (per-thread), then block-wide visibility
        if (ck <= NCHUNK - 3)      asm volatile("cp.async.wait_group 2;" ::: "memory");
        else if (ck == NCHUNK - 2) asm volatile("cp.async.wait_group 1;" ::: "memory");
        else                       asm volatile("cp.async.wait_group 0;" ::: "memory");
        __syncthreads();

        // issue 12 MMAs (3 split terms x 4 K-steps of 16)
        if (tid == 0) {
            const uint32_t stage_s = sb + 1024 + (ck % NSTAGE) * STAGE_BYTES;
            fence_proxy_async_shared();
            uint64_t dAh = make_desc_sw128(stage_s + OFF_A_HI);
            uint64_t dAl = make_desc_sw128(stage_s + OFF_A_LO);
            uint64_t dBh = make_desc_sw128(stage_s + OFF_B_HI);
            uint64_t dBl = make_desc_sw128(stage_s + OFF_B_LO);
#pragma unroll
            for (int k4 = 0; k4 < 4; k4++) {
                uint32_t en0 = (ck > 0 || k4 > 0) ? 1u : 0u;
                mma_f16_ss(tmem, dAh + k4 * 2, dBh + k4 * 2, IDESC, en0);
                mma_f16_ss(tmem, dAh + k4 * 2, dBl + k4 * 2, IDESC, 1u);
                mma_f16_ss(tmem, dAl + k4 * 2, dBh + k4 * 2, IDESC, 1u);
            }
            tc_commit(sb + 8 + 8 * (ck % NSTAGE));
        }
        // next iteration's buffer overwrite is gated by that buffer's mbar
    }

    // final: wait for chunk 16's MMA. stage = 16%3 = 1; arrivals on stage1 at
    // chunks 1,4,7,10,13,16 (6th) -> parity 1; loop consumed parities 0,1,0,1,0.
    mbar_wait(sb + 8 + 8 * ((NCHUNK - 1) % NSTAGE),
              (uint32_t)((((NCHUNK - 1) - ((NCHUNK - 1) % NSTAGE)) / NSTAGE) & 1));
    tc_fence_after();

    // ---- fused LSTM epilogue: 4 warps read D (M=128 rows x N=128 cols) ----
    if (wid < 4) {
        const int brow_g = bm0 + wid * 32 + lane;   // batch row
        const int cbase = brow_g * H_ + j0;
        const float* bs = (const float*)(smem + 256);
#pragma unroll
        for (int uh = 0; uh < UNITS; uh += 16) {
            uint32_t ri[16], rf[16], rg[16], ro[16];
            TC_LD_X16(ri, tmem + 0 + uh);
            TC_LD_X16(rf, tmem + 32 + uh);
            TC_LD_X16(rg, tmem + 64 + uh);
            TC_LD_X16(ro, tmem + 96 + uh);
            tc_wait_ld();

            float cnv[16], hnv[16];
#pragma unroll
            for (int u2 = 0; u2 < 16; u2++) {
                int u = uh + u2;
                float ig = __uint_as_float(ri[u2]) + bs[u];
                float fg = __uint_as_float(rf[u2]) + bs[32 + u];
                float gg = __uint_as_float(rg[u2]) + bs[64 + u];
                float og = __uint_as_float(ro[u2]) + bs[96 + u];
                float c_old = g_c[cbase + u];
                float cn = sigf(fg) * c_old + sigf(ig) * tanhf(gg);
                float hn = sigf(og) * tanhf(cn);
                cnv[u2] = cn;
                hnv[u2] = hn;
            }
            // vectorized stores
#pragma unroll
            for (int v = 0; v < 4; v++) {
                *(float4*)(g_c + cbase + uh + v * 4) =
                    make_float4(cnv[v * 4], cnv[v * 4 + 1], cnv[v * 4 + 2], cnv[v * 4 + 3]);
                *(float4*)(g_hall + (size_t)t * (B_ * H_) + cbase + uh + v * 4) =
                    make_float4(hnv[v * 4], hnv[v * 4 + 1], hnv[v * 4 + 2], hnv[v * 4 + 3]);
            }
            uint32_t hi_pack[8], lo_pack[8];
#pragma unroll
            for (int v = 0; v < 8; v++) {
                __nv_bfloat16 h0 = __float2bfloat16(hnv[v * 2]);
                __nv_bfloat16 h1 = __float2bfloat16(hnv[v * 2 + 1]);
                __nv_bfloat16 l0 = __float2bfloat16(hnv[v * 2] - __bfloat162float(h0));
                __nv_bfloat16 l1 = __float2bfloat16(hnv[v * 2 + 1] - __bfloat162float(h1));
                hi_pack[v] = ((uint32_t)__bfloat16_as_ushort(h1) << 16) | __bfloat16_as_ushort(h0);
                lo_pack[v] = ((uint32_t)__bfloat16_as_ushort(l1) << 16) | __bfloat16_as_ushort(l0);
            }
            *(uint4*)(&g_h_hi[nxt][cbase + uh]) =
                make_uint4(hi_pack[0], hi_pack[1], hi_pack[2], hi_pack[3]);
            *(uint4*)(&g_h_hi[nxt][cbase + uh + 8]) =
                make_uint4(hi_pack[4], hi_pack[5], hi_pack[6], hi_pack[7]);
            *(uint4*)(&g_h_lo[nxt][cbase + uh]) =
                make_uint4(lo_pack[0], lo_pack[1], lo_pack[2], lo_pack[3]);
            *(uint4*)(&g_h_lo[nxt][cbase + uh + 8]) =
                make_uint4(lo_pack[4], lo_pack[5], lo_pack[6], lo_pack[7]);
        }
        tc_fence_before();
    }
    __syncthreads();
    if (tid == 0) {
        mbar_inval(sb + 8);
        mbar_inval(sb + 16);
        mbar_inval(sb + 24);
    }
    __syncthreads();
    if (wid == 0) tmem_dealloc(tmem, 128);
#else
    // ---- correct (slow) SIMT fallback for the non-'a' compilation pass ----
    const int tid = threadIdx.x;
    const int bm0 = blockIdx.x * 128;
    const int j0 = blockIdx.y * UNITS;
    const int cur = t & 1, nxt = cur ^ 1;
    for (int o = tid; o < 128 * UNITS; o += 256) {
        int row = o / UNITS;
        int u = o % UNITS;
        int b = bm0 + row;
        int jg = j0 + u;
        float acc[4] = {0.f, 0.f, 0.f, 0.f};
        for (int k = 0; k < KTOT; k++) {
            float a;
            if (k < IN_) {
                size_t xo = ((size_t)t * B_ + b) * IN_ + k;
                a = __bfloat162float(g_x_hi[xo]) + __bfloat162float(g_x_lo[xo]);
            } else {
                size_t ho = (size_t)b * H_ + (k - IN_);
                a = __bfloat162float(g_h_hi[cur][ho]) + __bfloat162float(g_h_lo[cur][ho]);
            }
#pragma unroll
            for (int g = 0; g < 4; g++) {
                size_t wi = (size_t)(g * H_ + jg) * KTOT + k;
                acc[g] += a * (__bfloat162float(g_Wc_hi[wi]) + __bfloat162float(g_Wc_lo[wi]));
            }
        }
        float ig = acc[0] + bih[jg] + bhh[jg];
        float fg = acc[1] + bih[H_ + jg] + bhh[H_ + jg];
        float gg = acc[2] + bih[2 * H_ + jg] + bhh[2 * H_ + jg];
        float og = acc[3] + bih[3 * H_ + jg] + bhh[3 * H_ + jg];
        int idx = b * H_ + jg;
        float c_old = g_c[idx];
        float cn = sigf(fg) * c_old + sigf(ig) * tanhf(gg);
        float hn = sigf(og) * tanhf(cn);
        g_c[idx] = cn;
        g_hall[(size_t)t * (B_ * H_) + idx] = hn;
        __nv_bfloat16 hh = __float2bfloat16(hn);
        g_h_hi[nxt][idx] = hh;
        g_h_lo[nxt][idx] = __float2bfloat16(hn - __bfloat162float(hh));
    }
#endif
}

// ---------------- dense1: P = relu(h_all @ Wd^T + bd) ----------------
__global__ __launch_bounds__(256) void dense1(
    const float* __restrict__ Wd, const float* __restrict__ bd)
{
    __shared__ float As[8][132];
    __shared__ float Bs[8][132];
    const int tid = threadIdx.x;
    const int row0 = blockIdx.x * 128;
    const int lm = tid >> 1;
    const int lk = (tid & 1) << 2;
    const int m0 = (tid >> 4) << 3;
    const int n0 = (tid & 15) << 3;

    float acc[8][8];
#pragma unroll
    for (int i = 0; i < 8; i++)
#pragma unroll
        for (int j = 0; j < 8; j++) acc[i][j] = 0.f;

    for (int kk = 0; kk < H_; kk += 8) {
        float4 av = *(const float4*)(g_hall + (size_t)(row0 + lm) * H_ + kk + lk);
        float4 bv = *(const float4*)(Wd + (size_t)lm * H_ + kk + lk);
        __syncthreads();
        As[lk + 0][lm] = av.x; As[lk + 1][lm] = av.y;
        As[lk + 2][lm] = av.z; As[lk + 3][lm] = av.w;
        Bs[lk + 0][lm] = bv.x; Bs[lk + 1][lm] = bv.y;
        Bs[lk + 2][lm] = bv.z; Bs[lk + 3][lm] = bv.w;
        __syncthreads();
#pragma unroll
        for (int k = 0; k < 8; k++) {
            float4 a0 = *(const float4*)&As[k][m0];
            float4 a1 = *(const float4*)&As[k][m0 + 4];
            float4 b0 = *(const float4*)&Bs[k][n0];
            float4 b1 = *(const float4*)&Bs[k][n0 + 4];
            float a[8] = {a0.x, a0.y, a0.z, a0.w, a1.x, a1.y, a1.z, a1.w};
            float bb[8] = {b0.x, b0.y, b0.z, b0.w, b1.x, b1.y, b1.z, b1.w};
#pragma unroll
            for (int mi = 0; mi < 8; mi++)
#pragma unroll
                for (int ni = 0; ni < 8; ni++) acc[mi][ni] += a[mi] * bb[ni];
        }
    }
#pragma unroll
    for (int mi = 0; mi < 8; mi++) {
        size_t r = (size_t)(row0 + m0 + mi);
#pragma unroll
        for (int ni = 0; ni < 8; ni++) {
            int n = n0 + ni;
            float v = acc[mi][ni] + bd[n];
            g_P[r * HEAD_ + n] = v > 0.f ? v : 0.f;
        }
    }
}

// ---------------- dense2: out = P @ W2^T + b2 ----------------
__global__ __launch_bounds__(256) void dense2(
    const float* __restrict__ W2, const float* __restrict__ b2,
    float* __restrict__ out)
{
    __shared__ float As[16][68];
    __shared__ float Bs[16][68];
    const int tid = threadIdx.x;
    const int row0 = blockIdx.x * 64;
    const int lm = tid >> 2;
    const int lk = (tid & 3) << 2;
    const int m0 = (tid >> 4) << 2;
    const int n0 = (tid & 15) << 2;

    float acc[4][4];
#pragma unroll
    for (int i = 0; i < 4; i++)
#pragma unroll
        for (int j = 0; j < 4; j++) acc[i][j] = 0.f;

    for (int kk = 0; kk < HEAD_; kk += 16) {
        float4 av = *(const float4*)(g_P + (size_t)(row0 + lm) * HEAD_ + kk + lk);
        float4 bv = *(const float4*)(W2 + (size_t)lm * HEAD_ + kk + lk);
        __syncthreads();
        As[lk + 0][lm] = av.x; As[lk + 1][lm] = av.y;
        As[lk + 2][lm] = av.z; As[lk + 3][lm] = av.w;
        Bs[lk + 0][lm] = bv.x; Bs[lk + 1][lm] = bv.y;
        Bs[lk + 2][lm] = bv.z; Bs[lk + 3][lm] = bv.w;
        __syncthreads();
#pragma unroll
        for (int k = 0; k < 16; k++) {
            float4 a4 = *(const float4*)&As[k][m0];
            float4 b4 = *(const float4*)&Bs[k][n0];
            float a[4] = {a4.x, a4.y, a4.z, a4.w};
            float bb[4] = {b4.x, b4.y, b4.z, b4.w};
#pragma unroll
            for (int mi = 0; mi < 4; mi++)
#pragma unroll
                for (int ni = 0; ni < 4; ni++) acc[mi][ni] += a[mi] * bb[ni];
        }
    }
#pragma unroll
    for (int mi = 0; mi < 4; mi++) {
        int r = row0 + m0 + mi;
        int tt = r >> 8;
        int b = r & 255;
#pragma unroll
        for (int ni = 0; ni < 4; ni++) {
            int n = n0 + ni;
            out[((size_t)b * S_ + tt) * OUT_ + n] = acc[mi][ni] + b2[n];
        }
    }
}

// ---------------- launch ----------------
extern "C" void kernel_launch(void* const* d_in, const int* in_sizes, int n_in,
                              void* d_out, int out_size)
{
    const float* x   = (const float*)d_in[0];
    const float* Wih = (const float*)d_in[1];
    const float* bih = (const float*)d_in[2];
    const float* Whh = (const float*)d_in[3];
    const float* bhh = (const float*)d_in[4];
    const float* Wd  = (const float*)d_in[5];
    const float* bd  = (const float*)d_in[6];
    const float* W2  = (const float*)d_in[7];
    const float* b2  = (const float*)d_in[8];
    float* out = (float*)d_out;

    cudaFuncSetAttribute(lstm_step_tc, cudaFuncAttributeMaxDynamicSharedMemorySize, SMEM_TOTAL);

    prep_state<<<256, 256>>>();
    prep_w<<<512, 256>>>(Wih, Whh);
    prep_x<<<512, 256>>>(x);

    dim3 sg(2, 32);  // 64 CTAs
    for (int t = 0; t < S_; t++) {
        lstm_step_tc<<<sg, 256, SMEM_TOTAL>>>(bih, bhh, t);
    }

    dense1<<<(S_ * B_) / 128, 256>>>(Wd, bd);
    dense2<<<(S_ * B_) / 64, 256>>>(W2, b2, out);
}

// round 7
// speedup vs baseline: 3.5536x; 1.0586x over previous
#include <cuda_runtime.h>
#include <cuda_bf16.h>
#include <math.h>
#include <stdint.h>

#define B_   256
#define S_   512
#define IN_  64
#define H_   1024
#define G4   4096
#define KTOT 1088
#define HEAD_ 128
#define OUT_ 64
#define KC   64
#define NCHUNK 17
#define UNITS 32
#define NCTA 64

#if defined(__CUDA_ARCH_FEAT_SM103_ALL) || defined(__CUDA_ARCH_FEAT_SM100_ALL) || \
    (defined(__CUDA_ARCH_SPECIFIC__) && (__CUDA_ARCH_SPECIFIC__ >= 1000))
#define HAS_TCGEN05 1
#else
#define HAS_TCGEN05 0
#endif

// ---------------- device scratch ----------------
__device__ float g_c[B_ * H_];
__device__ __nv_bfloat16 g_hall_hi[(size_t)(S_ + 1) * B_ * H_];  // row (t+1)*B+b = h_t
__device__ __nv_bfloat16 g_hall_lo[(size_t)(S_ + 1) * B_ * H_];
__device__ __nv_bfloat16 g_Wc_hi[(size_t)G4 * KTOT];
__device__ __nv_bfloat16 g_Wc_lo[(size_t)G4 * KTOT];
__device__ __nv_bfloat16 g_x_hi[(size_t)S_ * B_ * IN_];
__device__ __nv_bfloat16 g_x_lo[(size_t)S_ * B_ * IN_];
__device__ __nv_bfloat16 g_Wd_hi[HEAD_ * H_];
__device__ __nv_bfloat16 g_Wd_lo[HEAD_ * H_];
__device__ __nv_bfloat16 g_W2_hi[OUT_ * HEAD_];
__device__ __nv_bfloat16 g_W2_lo[OUT_ * HEAD_];
__device__ unsigned g_sync_count;
__device__ unsigned g_sync_gen;

__device__ __forceinline__ float sigf(float x) { return 1.0f / (1.0f + expf(-x)); }
__device__ __forceinline__ uint32_t smem_u32(const void* p) {
    return (uint32_t)__cvta_generic_to_shared(p);
}

// -------- grid-wide barrier (all NCTA CTAs resident: 64 <= 148 SMs) --------
__device__ __forceinline__ void grid_sync() {
    __syncthreads();
    if (threadIdx.x == 0) {
        __threadfence();
        unsigned gen;
        asm volatile("ld.acquire.gpu.global.u32 %0, [%1];" : "=r"(gen) : "l"(&g_sync_gen));
        unsigned arrived = atomicAdd(&g_sync_count, 1);
        if (arrived == NCTA - 1) {
            atomicExch(&g_sync_count, 0);
            __threadfence();
            atomicAdd(&g_sync_gen, 1);
        } else {
            unsigned cur;
            do {
                __nanosleep(32);
                asm volatile("ld.acquire.gpu.global.u32 %0, [%1];" : "=r"(cur) : "l"(&g_sync_gen));
            } while (cur == gen);
        }
        __threadfence();
    }
    __syncthreads();
}

#if HAS_TCGEN05
__device__ __forceinline__ uint64_t make_desc_sw128(uint32_t addr) {
    return 0x4000404000010000ULL | (uint64_t)((addr >> 4) & 0x3FFF);
}
__device__ __forceinline__ void mbar_init(uint32_t mbar, uint32_t cnt) {
    asm volatile("mbarrier.init.shared.b64 [%0], %1;" :: "r"(mbar), "r"(cnt) : "memory");
}
__device__ __forceinline__ void mbar_inval(uint32_t mbar) {
    asm volatile("mbarrier.inval.shared.b64 [%0];" :: "r"(mbar) : "memory");
}
__device__ __forceinline__ void mbar_wait(uint32_t mbar, uint32_t parity) {
    asm volatile(
        "{\n\t.reg .pred P1;\n\t"
        "WAIT_LOOP_%=:\n\t"
        "mbarrier.try_wait.parity.acquire.cta.shared::cta.b64 P1, [%0], %1, 0x989680;\n\t"
        "@P1 bra.uni WAIT_DONE_%=;\n\t"
        "bra.uni WAIT_LOOP_%=;\n\t"
        "WAIT_DONE_%=:\n\t}"
        :: "r"(mbar), "r"(parity) : "memory");
}
__device__ __forceinline__ void tmem_alloc(uint32_t smem_res, uint32_t ncols) {
    asm volatile("tcgen05.alloc.cta_group::1.sync.aligned.shared::cta.b32 [%0], %1;"
                 :: "r"(smem_res), "r"(ncols) : "memory");
}
__device__ __forceinline__ void tmem_dealloc(uint32_t tmem, uint32_t ncols) {
    asm volatile("tcgen05.dealloc.cta_group::1.sync.aligned.b32 %0, %1;" :: "r"(tmem), "r"(ncols));
}
__device__ __forceinline__ void tmem_relinquish() {
    asm volatile("tcgen05.relinquish_alloc_permit.cta_group::1.sync.aligned;");
}
__device__ __forceinline__ void tc_commit(uint32_t mbar) {
    asm volatile("tcgen05.commit.cta_group::1.mbarrier::arrive::one.shared::cluster.b64 [%0];"
                 :: "r"(mbar) : "memory");
}
__device__ __forceinline__ void tc_fence_after() {
    asm volatile("tcgen05.fence::after_thread_sync;" ::: "memory");
}
__device__ __forceinline__ void tc_fence_before() {
    asm volatile("tcgen05.fence::before_thread_sync;" ::: "memory");
}
__device__ __forceinline__ void tc_wait_ld() {
    asm volatile("tcgen05.wait::ld.sync.aligned;" ::: "memory");
}
__device__ __forceinline__ void fence_proxy_async_shared() {
    asm volatile("fence.proxy.async.shared::cta;" ::: "memory");
}
__device__ __forceinline__ void mma_f16_ss(uint32_t d_tmem, uint64_t a_desc, uint64_t b_desc,
                                           uint32_t idesc, uint32_t enable) {
    asm volatile(
        "{\n\t.reg .pred p;\n\t"
        "setp.ne.u32 p, %4, 0;\n\t"
        "tcgen05.mma.cta_group::1.kind::f16 [%0], %1, %2, %3, {%5, %5, %5, %5}, p;\n\t}"
        :: "r"(d_tmem), "l"(a_desc), "l"(b_desc), "r"(idesc), "r"(enable), "r"(0u)
        : "memory");
}
__device__ __forceinline__ void cp16(uint32_t dst, const void* src) {
    asm volatile("cp.async.cg.shared.global [%0], [%1], 16;" :: "r"(dst), "l"(src));
}
__device__ __forceinline__ void cp_commit() {
    asm volatile("cp.async.commit_group;" ::: "memory");
}
#define TC_LD_X16(r, tmem_addr) \
    asm volatile( \
        "tcgen05.ld.sync.aligned.32x32b.x16.b32 " \
        "{%0, %1, %2, %3, %4, %5, %6, %7, " \
        " %8, %9, %10, %11, %12, %13, %14, %15}, [%16];" \
        : "=r"((r)[0]),  "=r"((r)[1]),  "=r"((r)[2]),  "=r"((r)[3]), \
          "=r"((r)[4]),  "=r"((r)[5]),  "=r"((r)[6]),  "=r"((r)[7]), \
          "=r"((r)[8]),  "=r"((r)[9]),  "=r"((r)[10]), "=r"((r)[11]), \
          "=r"((r)[12]), "=r"((r)[13]), "=r"((r)[14]), "=r"((r)[15]) \
        : "r"(tmem_addr))
#define TC_LD_X32(r, tmem_addr) \
    asm volatile( \
        "tcgen05.ld.sync.aligned.32x32b.x32.b32 " \
        "{%0, %1, %2, %3, %4, %5, %6, %7, " \
        " %8, %9, %10, %11, %12, %13, %14, %15, " \
        " %16, %17, %18, %19, %20, %21, %22, %23, " \
        " %24, %25, %26, %27, %28, %29, %30, %31}, [%32];" \
        : "=r"((r)[0]),  "=r"((r)[1]),  "=r"((r)[2]),  "=r"((r)[3]), \
          "=r"((r)[4]),  "=r"((r)[5]),  "=r"((r)[6]),  "=r"((r)[7]), \
          "=r"((r)[8]),  "=r"((r)[9]),  "=r"((r)[10]), "=r"((r)[11]), \
          "=r"((r)[12]), "=r"((r)[13]), "=r"((r)[14]), "=r"((r)[15]), \
          "=r"((r)[16]), "=r"((r)[17]), "=r"((r)[18]), "=r"((r)[19]), \
          "=r"((r)[20]), "=r"((r)[21]), "=r"((r)[22]), "=r"((r)[23]), \
          "=r"((r)[24]), "=r"((r)[25]), "=r"((r)[26]), "=r"((r)[27]), \
          "=r"((r)[28]), "=r"((r)[29]), "=r"((r)[30]), "=r"((r)[31]) \
        : "r"(tmem_addr))
#endif  // HAS_TCGEN05

// idesc: F32 accum | BF16 a | BF16 b | N | M=128
#define IDESC_N128 ((1u << 4) | (1u << 7) | (1u << 10) | (16u << 17) | (8u << 24))
#define IDESC_N64  ((1u << 4) | (1u << 7) | (1u << 10) | (8u << 17)  | (8u << 24))

// LSTM kernel SMEM: ctrl 1KB + 3 stages x 64KB
#define STAGE_BYTES 65536
#define OFF_A_HI 0
#define OFF_A_LO 16384
#define OFF_B_HI 32768
#define OFF_B_LO 49152
#define SMEM_LSTM (1024 + 3 * STAGE_BYTES)

// Head kernel SMEM: ctrl 1KB + W2 32KB + 3 stages x 64KB (P overlays stage 0)
#define HW2_BASE   1024
#define HSTAGE0    33792
#define SMEM_HEAD  (HSTAGE0 + 3 * STAGE_BYTES)   // 230400 <= 232448

// ---------------- prep kernels ----------------
__global__ void prep_misc(const float* __restrict__ Wd, const float* __restrict__ W2) {
    for (int i = blockIdx.x * blockDim.x + threadIdx.x; i < B_ * H_;
         i += gridDim.x * blockDim.x) {
        g_c[i] = 0.f;
        g_hall_hi[i] = __float2bfloat16(0.f);
        g_hall_lo[i] = __float2bfloat16(0.f);
        if (i < HEAD_ * H_) {
            float v = Wd[i];
            __nv_bfloat16 hi = __float2bfloat16(v);
            g_Wd_hi[i] = hi;
            g_Wd_lo[i] = __float2bfloat16(v - __bfloat162float(hi));
        }
        if (i < OUT_ * HEAD_) {
            float v = W2[i];
            __nv_bfloat16 hi = __float2bfloat16(v);
            g_W2_hi[i] = hi;
            g_W2_lo[i] = __float2bfloat16(v - __bfloat162float(hi));
        }
        if (i == 0) { g_sync_count = 0; g_sync_gen = 0; }
    }
}
__global__ void prep_w(const float* __restrict__ Wih, const float* __restrict__ Whh) {
    const size_t n = (size_t)G4 * KTOT;
    for (size_t i = blockIdx.x * blockDim.x + threadIdx.x; i < n;
         i += (size_t)gridDim.x * blockDim.x) {
        int r = (int)(i / KTOT);
        int k = (int)(i - (size_t)r * KTOT);
        float v = (k < IN_) ? Wih[(size_t)r * IN_ + k] : Whh[(size_t)r * H_ + (k - IN_)];
        __nv_bfloat16 hi = __float2bfloat16(v);
        g_Wc_hi[i] = hi;
        g_Wc_lo[i] = __float2bfloat16(v - __bfloat162float(hi));
    }
}
__global__ void prep_x(const float* __restrict__ x) {
    const size_t n = (size_t)S_ * B_ * IN_;
    for (size_t i = blockIdx.x * blockDim.x + threadIdx.x; i < n;
         i += (size_t)gridDim.x * blockDim.x) {
        int t = (int)(i / (B_ * IN_));
        int rem = (int)(i - (size_t)t * (B_ * IN_));
        int b = rem / IN_;
        int ii = rem - b * IN_;
        float v = x[((size_t)b * S_ + t) * IN_ + ii];
        __nv_bfloat16 hi = __float2bfloat16(v);
        g_x_hi[i] = hi;
        g_x_lo[i] = __float2bfloat16(v - __bfloat162float(hi));
    }
}

// ---------------- persistent tcgen05 LSTM ----------------
// Grid 64 CTAs: m = bid&1 (128 batch rows), jtile = bid>>1 (32 hidden units).
__global__ void __launch_bounds__(256, 1) lstm_persist(
    const float* __restrict__ bih, const float* __restrict__ bhh)
{
#if HAS_TCGEN05
    extern __shared__ char smem[];
    const uint32_t sb = smem_u32(smem);
    const int tid = threadIdx.x;
    const int wid = tid >> 5;
    const int lane = tid & 31;
    const int bm0 = (blockIdx.x & 1) * 128;
    const int j0 = (blockIdx.x >> 1) * UNITS;

    if (wid == 0) { tmem_alloc(sb, 128); tmem_relinquish(); }
    if (tid == 0) { mbar_init(sb + 8, 1); mbar_init(sb + 16, 1); mbar_init(sb + 24, 1); }
    if (tid < 128) {
        int grow = ((tid >> 5) << 10) + j0 + (tid & 31);
        ((float*)(smem + 256))[tid] = bih[grow] + bhh[grow];
    }
    __syncthreads();
    const uint32_t tmem = *(const uint32_t*)smem;

    uint32_t wp[3] = {0, 0, 0};

    for (int t = 0; t < S_; t++) {
        auto load_chunk = [&](int cn, int buf) {
            const uint32_t st = sb + 1024 + buf * STAGE_BYTES;
#pragma unroll
            for (int q = 0; q < 4; q++) {
                int slot = tid + q * 256;
                int row = slot >> 3, c16 = slot & 7;
                uint32_t off = row * 128 + c16 * 16;
                uint32_t sw = off ^ ((off >> 3) & 0x70);
                const __nv_bfloat16 *ah, *al;
                if (cn == 0) {
                    size_t o = ((size_t)t * B_ + bm0 + row) * IN_ + c16 * 8;
                    ah = g_x_hi + o; al = g_x_lo + o;
                } else {
                    size_t o = ((size_t)t * B_ + bm0 + row) * H_ + (cn - 1) * KC + c16 * 8;
                    ah = g_hall_hi + o; al = g_hall_lo + o;
                }
                cp16(st + OFF_A_HI + sw, ah);
                cp16(st + OFF_A_LO + sw, al);
                int grow = ((row >> 5) << 10) + j0 + (row & 31);
                size_t ob = (size_t)grow * KTOT + cn * KC + c16 * 8;
                cp16(st + OFF_B_HI + sw, g_Wc_hi + ob);
                cp16(st + OFF_B_LO + sw, g_Wc_lo + ob);
            }
            cp_commit();
        };

        load_chunk(0, 0);
        load_chunk(1, 1);

#pragma unroll
        for (int ck = 0; ck < NCHUNK; ck++) {
            const int cn = ck + 2;
            if (cn <= NCHUNK - 1) {
                const int b = cn % 3;
                if (cn >= 3) { mbar_wait(sb + 8 + 8 * b, wp[b]); wp[b] ^= 1; }
                load_chunk(cn, b);
            }
            if (ck <= NCHUNK - 3)      asm volatile("cp.async.wait_group 2;" ::: "memory");
            else if (ck == NCHUNK - 2) asm volatile("cp.async.wait_group 1;" ::: "memory");
            else                       asm volatile("cp.async.wait_group 0;" ::: "memory");
            __syncthreads();

            if (tid == 0) {
                const uint32_t st = sb + 1024 + (ck % 3) * STAGE_BYTES;
                fence_proxy_async_shared();
                uint64_t dAh = make_desc_sw128(st + OFF_A_HI);
                uint64_t dAl = make_desc_sw128(st + OFF_A_LO);
                uint64_t dBh = make_desc_sw128(st + OFF_B_HI);
                uint64_t dBl = make_desc_sw128(st + OFF_B_LO);
#pragma unroll
                for (int k4 = 0; k4 < 4; k4++) {
                    uint32_t en0 = (ck > 0 || k4 > 0) ? 1u : 0u;
                    mma_f16_ss(tmem, dAh + k4 * 2, dBh + k4 * 2, IDESC_N128, en0);
                    mma_f16_ss(tmem, dAh + k4 * 2, dBl + k4 * 2, IDESC_N128, 1u);
                    mma_f16_ss(tmem, dAl + k4 * 2, dBh + k4 * 2, IDESC_N128, 1u);
                }
                tc_commit(sb + 8 + 8 * (ck % 3));
            }
        }

        // final wait: chunk 16 committed on stage 1 (16%3). commits 14 (s2) and
        // 15 (s0) are unconsumed -> manual parity flips (buffers known free).
        mbar_wait(sb + 16, wp[1]); wp[1] ^= 1;
        wp[0] ^= 1; wp[2] ^= 1;
        tc_fence_after();

        if (wid < 4) {
            const int brow = bm0 + wid * 32 + lane;
            const int cbase = brow * H_ + j0;
            const size_t hbase = ((size_t)(t + 1) * B_ + brow) * H_ + j0;
            const float* bs = (const float*)(smem + 256);
#pragma unroll
            for (int uh = 0; uh < UNITS; uh += 16) {
                uint32_t ri[16], rf[16], rg[16], ro[16];
                TC_LD_X16(ri, tmem + 0 + uh);
                TC_LD_X16(rf, tmem + 32 + uh);
                TC_LD_X16(rg, tmem + 64 + uh);
                TC_LD_X16(ro, tmem + 96 + uh);
                tc_wait_ld();

                float cold[16];
#pragma unroll
                for (int v = 0; v < 4; v++)
                    *(float4*)&cold[v * 4] = *(const float4*)(g_c + cbase + uh + v * 4);

                float cnv[16], hnv[16];
#pragma unroll
                for (int u2 = 0; u2 < 16; u2++) {
                    int u = uh + u2;
                    float ig = __uint_as_float(ri[u2]) + bs[u];
                    float fg = __uint_as_float(rf[u2]) + bs[32 + u];
                    float gg = __uint_as_float(rg[u2]) + bs[64 + u];
                    float og = __uint_as_float(ro[u2]) + bs[96 + u];
                    float cn = sigf(fg) * cold[u2] + sigf(ig) * tanhf(gg);
                    cnv[u2] = cn;
                    hnv[u2] = sigf(og) * tanhf(cn);
                }
#pragma unroll
                for (int v = 0; v < 4; v++)
                    *(float4*)(g_c + cbase + uh + v * 4) =
                        make_float4(cnv[v * 4], cnv[v * 4 + 1], cnv[v * 4 + 2], cnv[v * 4 + 3]);
                uint32_t hp[8], lp[8];
#pragma unroll
                for (int v = 0; v < 8; v++) {
                    __nv_bfloat16 h0 = __float2bfloat16(hnv[v * 2]);
                    __nv_bfloat16 h1 = __float2bfloat16(hnv[v * 2 + 1]);
                    __nv_bfloat16 l0 = __float2bfloat16(hnv[v * 2] - __bfloat162float(h0));
                    __nv_bfloat16 l1 = __float2bfloat16(hnv[v * 2 + 1] - __bfloat162float(h1));
                    hp[v] = ((uint32_t)__bfloat16_as_ushort(h1) << 16) | __bfloat16_as_ushort(h0);
                    lp[v] = ((uint32_t)__bfloat16_as_ushort(l1) << 16) | __bfloat16_as_ushort(l0);
                }
                *(uint4*)(&g_hall_hi[hbase + uh])     = make_uint4(hp[0], hp[1], hp[2], hp[3]);
                *(uint4*)(&g_hall_hi[hbase + uh + 8]) = make_uint4(hp[4], hp[5], hp[6], hp[7]);
                *(uint4*)(&g_hall_lo[hbase + uh])     = make_uint4(lp[0], lp[1], lp[2], lp[3]);
                *(uint4*)(&g_hall_lo[hbase + uh + 8]) = make_uint4(lp[4], lp[5], lp[6], lp[7]);
            }
            tc_fence_before();
        }
        grid_sync();
    }

    __syncthreads();
    if (tid == 0) { mbar_inval(sb + 8); mbar_inval(sb + 16); mbar_inval(sb + 24); }
    __syncthreads();
    if (wid == 0) tmem_dealloc(tmem, 128);
#else
    // correct SIMT fallback (never runs on GB300)
    const int tid = threadIdx.x;
    const int bm0 = (blockIdx.x & 1) * 128;
    const int j0 = (blockIdx.x >> 1) * UNITS;
    for (int t = 0; t < S_; t++) {
        for (int o = tid; o < 128 * UNITS; o += 256) {
            int row = o / UNITS, u = o % UNITS;
            int b = bm0 + row, jg = j0 + u;
            float acc[4] = {0.f, 0.f, 0.f, 0.f};
            for (int k = 0; k < KTOT; k++) {
                float a;
                if (k < IN_) {
                    size_t xo = ((size_t)t * B_ + b) * IN_ + k;
                    a = __bfloat162float(g_x_hi[xo]) + __bfloat162float(g_x_lo[xo]);
                } else {
                    size_t ho = ((size_t)t * B_ + b) * H_ + (k - IN_);
                    a = __bfloat162float(g_hall_hi[ho]) + __bfloat162float(g_hall_lo[ho]);
                }
#pragma unroll
                for (int g = 0; g < 4; g++) {
                    size_t wi = (size_t)(g * H_ + jg) * KTOT + k;
                    acc[g] += a * (__bfloat162float(g_Wc_hi[wi]) + __bfloat162float(g_Wc_lo[wi]));
                }
            }
            float ig = acc[0] + bih[jg] + bhh[jg];
            float fg = acc[1] + bih[H_ + jg] + bhh[H_ + jg];
            float gg = acc[2] + bih[2 * H_ + jg] + bhh[2 * H_ + jg];
            float og = acc[3] + bih[3 * H_ + jg] + bhh[3 * H_ + jg];
            int idx = b * H_ + jg;
            float cn = sigf(fg) * g_c[idx] + sigf(ig) * tanhf(gg);
            float hn = sigf(og) * tanhf(cn);
            g_c[idx] = cn;
            size_t hb = ((size_t)(t + 1) * B_ + b) * H_ + jg;
            __nv_bfloat16 hh = __float2bfloat16(hn);
            g_hall_hi[hb] = hh;
            g_hall_lo[hb] = __float2bfloat16(hn - __bfloat162float(hh));
        }
        grid_sync();
    }
#endif
}

// ---------------- fused tcgen05 dense head ----------------
// Grid 1024 CTAs: each owns 128 rows r0..r0+127 (row = t*B + b).
// GEMM1: P = relu(h @ Wd^T + bd) -> SMEM; GEMM2: out = P @ W2^T + b2.
__global__ void __launch_bounds__(256, 1) head_tc(
    const float* __restrict__ bd, const float* __restrict__ b2, float* __restrict__ out)
{
#if HAS_TCGEN05
    extern __shared__ char smem[];
    const uint32_t sb = smem_u32(smem);
    const int tid = threadIdx.x;
    const int wid = tid >> 5;
    const int lane = tid & 31;
    const int r0 = blockIdx.x * 128;

    if (wid == 0) { tmem_alloc(sb, 256); tmem_relinquish(); }
    if (tid == 0) { mbar_init(sb + 8, 1); mbar_init(sb + 16, 1); mbar_init(sb + 24, 1); }
    if (tid < 128) ((float*)(smem + 256))[tid] = bd[tid];
    if (tid < 64)  ((float*)(smem + 768))[tid] = b2[tid];
    // W2 hi/lo -> SMEM, SW128, 2 K-chunks of 64
    for (int i = tid; i < 64 * 16; i += 256) {
        int row = i >> 4;
        int col = (i & 15) * 8;
        int chunk = col >> 6, kin = col & 63;
        uint32_t off = row * 128 + kin * 2;
        uint32_t sw = off ^ ((off >> 3) & 0x70);
        *(uint4*)(smem + HW2_BASE + chunk * 8192 + sw) =
            *(const uint4*)(g_W2_hi + row * HEAD_ + col);
        *(uint4*)(smem + HW2_BASE + 16384 + chunk * 8192 + sw) =
            *(const uint4*)(g_W2_lo + row * HEAD_ + col);
    }
    __syncthreads();
    const uint32_t tmem = *(const uint32_t*)smem;

    auto load_chunk = [&](int cn, int buf) {
        const uint32_t st = sb + HSTAGE0 + buf * STAGE_BYTES;
#pragma unroll
        for (int q = 0; q < 4; q++) {
            int slot = tid + q * 256;
            int row = slot >> 3, c16 = slot & 7;
            uint32_t off = row * 128 + c16 * 16;
            uint32_t sw = off ^ ((off >> 3) & 0x70);
            size_t oa = ((size_t)(B_ + r0 + row)) * H_ + cn * KC + c16 * 8;
            cp16(st + OFF_A_HI + sw, g_hall_hi + oa);
            cp16(st + OFF_A_LO + sw, g_hall_lo + oa);
            size_t ob = (size_t)row * H_ + cn * KC + c16 * 8;
            cp16(st + OFF_B_HI + sw, g_Wd_hi + ob);
            cp16(st + OFF_B_LO + sw, g_Wd_lo + ob);
        }
        cp_commit();
    };

    uint32_t wp[3] = {0, 0, 0};
    load_chunk(0, 0);
    load_chunk(1, 1);
#pragma unroll
    for (int ck = 0; ck < 16; ck++) {
        const int cn = ck + 2;
        if (cn <= 15) {
            const int b = cn % 3;
            if (cn >= 3) { mbar_wait(sb + 8 + 8 * b, wp[b]); wp[b] ^= 1; }
            load_chunk(cn, b);
        }
        if (ck <= 13)      asm volatile("cp.async.wait_group 2;" ::: "memory");
        else if (ck == 14) asm volatile("cp.async.wait_group 1;" ::: "memory");
        else               asm volatile("cp.async.wait_group 0;" ::: "memory");
        __syncthreads();
        if (tid == 0) {
            const uint32_t st = sb + HSTAGE0 + (ck % 3) * STAGE_BYTES;
            fence_proxy_async_shared();
            uint64_t dAh = make_desc_sw128(st + OFF_A_HI);
            uint64_t dAl = make_desc_sw128(st + OFF_A_LO);
            uint64_t dBh = make_desc_sw128(st + OFF_B_HI);
            uint64_t dBl = make_desc_sw128(st + OFF_B_LO);
#pragma unroll
            for (int k4 = 0; k4 < 4; k4++) {
                uint32_t en0 = (ck > 0 || k4 > 0) ? 1u : 0u;
                mma_f16_ss(tmem, dAh + k4 * 2, dBh + k4 * 2, IDESC_N128, en0);
                mma_f16_ss(tmem, dAh + k4 * 2, dBl + k4 * 2, IDESC_N128, 1u);
                mma_f16_ss(tmem, dAl + k4 * 2, dBh + k4 * 2, IDESC_N128, 1u);
            }
            tc_commit(sb + 8 + 8 * (ck % 3));
        }
    }
    // final GEMM1 wait: chunk 15 on stage 0; chunks 13 (s1), 14 (s2) unconsumed.
    mbar_wait(sb + 8, wp[0]); wp[0] ^= 1;
    wp[1] ^= 1; wp[2] ^= 1;
    tc_fence_after();

    // epilogue 1: relu(D1 + bd) -> bf16 hi/lo into P (stage-0 SMEM area)
    if (wid < 4) {
        const int rowl = wid * 32 + lane;
        const float* bds = (const float*)(smem + 256);
#pragma unroll
        for (int cb = 0; cb < 4; cb++) {
            uint32_t r[32];
            TC_LD_X32(r, tmem + cb * 32);
            tc_wait_ld();
#pragma unroll
            for (int c = 0; c < 32; c++) {
                int col = cb * 32 + c;
                float v = __uint_as_float(r[c]) + bds[col];
                v = fmaxf(v, 0.f);
                __nv_bfloat16 hi = __float2bfloat16(v);
                __nv_bfloat16 lo = __float2bfloat16(v - __bfloat162float(hi));
                int chunk = col >> 6, kin = col & 63;
                uint32_t off = rowl * 128 + kin * 2;
                uint32_t sw = off ^ ((off >> 3) & 0x70);
                *(__nv_bfloat16*)(smem + HSTAGE0 + chunk * 16384 + sw) = hi;
                *(__nv_bfloat16*)(smem + HSTAGE0 + 32768 + chunk * 16384 + sw) = lo;
            }
        }
        tc_fence_before();
    }
    __syncthreads();

    // GEMM2: out_tile = P @ W2^T  (M=128, N=64, K=128 -> 2 chunks)
    if (tid == 0) {
        fence_proxy_async_shared();
#pragma unroll
        for (int c = 0; c < 2; c++) {
            uint64_t dPh = make_desc_sw128(sb + HSTAGE0 + c * 16384);
            uint64_t dPl = make_desc_sw128(sb + HSTAGE0 + 32768 + c * 16384);
            uint64_t dWh = make_desc_sw128(sb + HW2_BASE + c * 8192);
            uint64_t dWl = make_desc_sw128(sb + HW2_BASE + 16384 + c * 8192);
#pragma unroll
            for (int k4 = 0; k4 < 4; k4++) {
                uint32_t en0 = (c > 0 || k4 > 0) ? 1u : 0u;
                mma_f16_ss(tmem + 128, dPh + k4 * 2, dWh + k4 * 2, IDESC_N64, en0);
                mma_f16_ss(tmem + 128, dPh + k4 * 2, dWl + k4 * 2, IDESC_N64, 1u);
                mma_f16_ss(tmem + 128, dPl + k4 * 2, dWh + k4 * 2, IDESC_N64, 1u);
            }
        }
        tc_commit(sb + 8);
    }
    mbar_wait(sb + 8, wp[0]); wp[0] ^= 1;
    tc_fence_after();

    // epilogue 2: out = D2 + b2
    if (wid < 4) {
        uint32_t d[64];
        TC_LD_X32(d, tmem + 128);
        TC_LD_X32(d + 32, tmem + 160);
        tc_wait_ld();
        tc_fence_before();
        const float* b2s = (const float*)(smem + 768);
        int r = r0 + wid * 32 + lane;
        int tt = r >> 8;
        int b = r & 255;
        float* op = out + ((size_t)b * S_ + tt) * OUT_;
#pragma unroll
        for (int v = 0; v < 16; v++) {
            *(float4*)(op + v * 4) = make_float4(
                __uint_as_float(d[v * 4 + 0]) + b2s[v * 4 + 0],
                __uint_as_float(d[v * 4 + 1]) + b2s[v * 4 + 1],
                __uint_as_float(d[v * 4 + 2]) + b2s[v * 4 + 2],
                __uint_as_float(d[v * 4 + 3]) + b2s[v * 4 + 3]);
        }
    }
    __syncthreads();
    if (tid == 0) { mbar_inval(sb + 8); mbar_inval(sb + 16); mbar_inval(sb + 24); }
    __syncthreads();
    if (wid == 0) tmem_dealloc(tmem, 256);
#else
    // correct SIMT fallback (never runs on GB300)
    const int tid = threadIdx.x;
    const int r0 = blockIdx.x * 128;
    for (int rl = tid; rl < 128; rl += 256) {
        int r = r0 + rl;
        float p[HEAD_];
        for (int n = 0; n < HEAD_; n++) {
            float acc = bd[n];
            for (int k = 0; k < H_; k++) {
                size_t ho = ((size_t)(B_ + r)) * H_ + k;
                float hv = __bfloat162float(g_hall_hi[ho]) + __bfloat162float(g_hall_lo[ho]);
                float wv = __bfloat162float(g_Wd_hi[n * H_ + k]) +
                           __bfloat162float(g_Wd_lo[n * H_ + k]);
                acc += hv * wv;
            }
            p[n] = acc > 0.f ? acc : 0.f;
        }
        int tt = r >> 8, b = r & 255;
        for (int n = 0; n < OUT_; n++) {
            float acc = b2[n];
            for (int k = 0; k < HEAD_; k++) {
                float wv = __bfloat162float(g_W2_hi[n * HEAD_ + k]) +
                           __bfloat162float(g_W2_lo[n * HEAD_ + k]);
                acc += p[k] * wv;
            }
            out[((size_t)b * S_ + tt) * OUT_ + n] = acc;
        }
    }
#endif
}

// ---------------- launch ----------------
extern "C" void kernel_launch(void* const* d_in, const int* in_sizes, int n_in,
                              void* d_out, int out_size)
{
    const float* x   = (const float*)d_in[0];
    const float* Wih = (const float*)d_in[1];
    const float* bih = (const float*)d_in[2];
    const float* Whh = (const float*)d_in[3];
    const float* bhh = (const float*)d_in[4];
    const float* Wd  = (const float*)d_in[5];
    const float* bd  = (const float*)d_in[6];
    const float* W2  = (const float*)d_in[7];
    const float* b2  = (const float*)d_in[8];
    float* out = (float*)d_out;

    cudaFuncSetAttribute(lstm_persist, cudaFuncAttributeMaxDynamicSharedMemorySize, SMEM_LSTM);
    cudaFuncSetAttribute(head_tc, cudaFuncAttributeMaxDynamicSharedMemorySize, SMEM_HEAD);

    prep_misc<<<512, 256>>>(Wd, W2);
    prep_w<<<512, 256>>>(Wih, Whh);
    prep_x<<<512, 256>>>(x);

    lstm_persist<<<NCTA, 256, SMEM_LSTM>>>(bih, bhh);
    head_tc<<<(S_ * B_) / 128, 256, SMEM_HEAD>>>(bd, b2, out);
}